// round 5
// baseline (speedup 1.0000x reference)
#include <cuda_runtime.h>
#include <cstdint>

#define N_FEATURES 16
#define N_CLASSES 10
#define MAX_DEPTH 10
#define N_INTERNAL 1023
#define N_LEAVES 1024
#define BLOCK 512
#define GRID 456   // 3 CTAs/SM x 152 SMs
#define ROW_STRIDE 11   // leaf row stride in floats (odd -> bank-spread gathers)

// Dynamic smem layout (bytes):
//   [0,     4096)  int   feat_s[1023]
//   [4096,  8192)  float thr_s[1023]
//   [8192, 53248)  float lv_s[1024*11]  (leaf rows padded to 11 floats)
#define SMEM_BYTES 53248

__global__ __launch_bounds__(BLOCK, 3)
void dtree_kernel(const float* __restrict__ X,
                  const int* __restrict__ tfeat,
                  const float* __restrict__ tthr,
                  const float* __restrict__ tval,
                  float* __restrict__ out,
                  int n)
{
    extern __shared__ char smem_raw[];
    int*   feat_s = reinterpret_cast<int*>(smem_raw);
    float* thr_s  = reinterpret_cast<float*>(smem_raw + 4096);
    float* lv_s   = reinterpret_cast<float*>(smem_raw + 8192);

    const int tid = threadIdx.x;

    for (int i = tid; i < N_INTERNAL; i += BLOCK) {
        feat_s[i] = tfeat[i];
        thr_s[i]  = tthr[i];
    }
    // Leaf rows (nodes 1023..2046) -> smem with stride-11 padding
    for (int idx = tid; idx < N_LEAVES * N_CLASSES; idx += BLOCK) {
        int r = idx / N_CLASSES;
        int c = idx - r * N_CLASSES;
        lv_s[r * ROW_STRIDE + c] = tval[(size_t)(N_INTERNAL + r) * N_CLASSES + c];
    }
    __syncthreads();

    const int lane   = tid & 31;
    const int stride = gridDim.x * BLOCK;

    for (int i = blockIdx.x * BLOCK + tid; i < n; i += stride) {
        // 16 features in registers
        const float4* __restrict__ xr = reinterpret_cast<const float4*>(X + (size_t)i * N_FEATURES);
        float4 a = xr[0], b = xr[1], c = xr[2], d = xr[3];

        int node = 0;
        #pragma unroll
        for (int lvl = 0; lvl < MAX_DEPTH; ++lvl) {
            const int   f   = feat_s[node];   // LDS.32, all 32 banks
            const float thr = thr_s[node];    // LDS.32, all 32 banks
            const bool b0 = (f & 1) != 0;
            const bool b1 = (f & 2) != 0;
            const bool b2 = (f & 4) != 0;
            const bool b3 = (f & 8) != 0;
            // 4-bit binary select tree over register-resident features
            float s0 = b0 ? a.y : a.x;
            float s1 = b0 ? a.w : a.z;
            float s2 = b0 ? b.y : b.x;
            float s3 = b0 ? b.w : b.z;
            float s4 = b0 ? c.y : c.x;
            float s5 = b0 ? c.w : c.z;
            float s6 = b0 ? d.y : d.x;
            float s7 = b0 ? d.w : d.z;
            float t0 = b1 ? s1 : s0;
            float t1 = b1 ? s3 : s2;
            float t2 = b1 ? s5 : s4;
            float t3 = b1 ? s7 : s6;
            float u0 = b2 ? t1 : t0;
            float u1 = b2 ? t3 : t2;
            float xv = b3 ? u1 : u0;
            node = 2 * node + 1 + ((xv > thr) ? 1 : 0);
        }

        // Leaf row base in smem floats (stride 11), shared via shuffle
        const int myrb = (node - N_INTERNAL) * ROW_STRIDE;

        // Warp-cooperative coalesced epilogue at float granularity:
        // 320 floats per warp; each LDS.32 instr spans ~3 rows of 10
        // consecutive odd-stride words -> near-conflict-free.
        float* __restrict__ orow = out + (size_t)(i - lane) * N_CLASSES;
        #pragma unroll
        for (int k = 0; k < 10; ++k) {
            int e = k * 32 + lane;          // 0..319
            int s = e / 10;                 // sample within warp batch
            int cc = e - s * 10;            // class index within row
            int rb = __shfl_sync(0xffffffffu, myrb, s);
            orow[e] = lv_s[rb + cc];
        }
    }
}

extern "C" void kernel_launch(void* const* d_in, const int* in_sizes, int n_in,
                              void* d_out, int out_size)
{
    const float* X     = (const float*)d_in[0];
    const int*   tfeat = (const int*)  d_in[1];
    const float* tthr  = (const float*)d_in[2];
    // d_in[3]/d_in[4] (left/right): implicit complete binary tree
    const float* tval  = (const float*)d_in[5];
    // d_in[6] (is_leaf): redundant at depth 10

    float* out = (float*)d_out;
    int n = in_sizes[0] / N_FEATURES;

    static bool attr_set = false;
    if (!attr_set) {
        cudaFuncSetAttribute(dtree_kernel,
                             cudaFuncAttributeMaxDynamicSharedMemorySize, SMEM_BYTES);
        attr_set = true;
    }

    int blocks = (n + BLOCK - 1) / BLOCK;
    if (blocks > GRID) blocks = GRID;

    dtree_kernel<<<blocks, BLOCK, SMEM_BYTES>>>(X, tfeat, tthr, tval, out, n);
}

// round 6
// speedup vs baseline: 1.0016x; 1.0016x over previous
#include <cuda_runtime.h>
#include <cstdint>

#define N_FEATURES 16
#define N_CLASSES 10
#define MAX_DEPTH 10
#define N_INTERNAL 1023
#define N_LEAVES 1024
#define BLOCK 256
#define GRID 608   // 4 CTAs/SM x 152 SMs

// Dynamic smem layout (bytes):
//   [0,     8184)  int2 nodes[1023]        {feature, threshold-bits}
//   [8192, 49152)  float2 leafvals[5120]   (1024 leaf rows x 5 float2)
#define SMEM_BYTES 49152

__global__ __launch_bounds__(BLOCK, 4)
void dtree_kernel(const float* __restrict__ X,
                  const int* __restrict__ tfeat,
                  const float* __restrict__ tthr,
                  const float* __restrict__ tval,
                  float* __restrict__ out,
                  int n)
{
    extern __shared__ char smem_raw[];
    int2*   nodes_s = reinterpret_cast<int2*>(smem_raw);
    float2* lv_s    = reinterpret_cast<float2*>(smem_raw + 8192);

    const int tid = threadIdx.x;

    for (int i = tid; i < N_INTERNAL; i += BLOCK)
        nodes_s[i] = make_int2(tfeat[i], __float_as_int(tthr[i]));
    {
        const float2* tv2 = reinterpret_cast<const float2*>(tval) + (N_INTERNAL * N_CLASSES) / 2;
        for (int i = tid; i < (N_LEAVES * N_CLASSES) / 2; i += BLOCK)
            lv_s[i] = tv2[i];
    }
    __syncthreads();

    const int lane   = tid & 31;
    const int stride = gridDim.x * BLOCK * 2;   // two samples per thread per iter

    for (int i0 = blockIdx.x * (BLOCK * 2) + tid; i0 < n; i0 += stride) {
        const int i1 = i0 + BLOCK;
        const bool has1 = (i1 < n);   // uniform across CTA (n % 256 == 0 assumed; guarded anyway)

        const float4* __restrict__ xr0 = reinterpret_cast<const float4*>(X + (size_t)i0 * N_FEATURES);
        float4 a0 = xr0[0], b0 = xr0[1], c0 = xr0[2], d0 = xr0[3];
        float4 a1, b1, c1, d1;
        if (has1) {
            const float4* __restrict__ xr1 = reinterpret_cast<const float4*>(X + (size_t)i1 * N_FEATURES);
            a1 = xr1[0]; b1 = xr1[1]; c1 = xr1[2]; d1 = xr1[3];
        } else {
            a1 = a0; b1 = b0; c1 = c0; d1 = d0;
        }

        int node0 = 0, node1 = 0;
        #pragma unroll
        for (int lvl = 0; lvl < MAX_DEPTH; ++lvl) {
            // Two independent dependent-chains, interleaved for ILP
            int2 nd0 = nodes_s[node0];
            int2 nd1 = nodes_s[node1];

            const int f0 = nd0.x;
            const int f1 = nd1.x;

            float p0 = (f0 & 1) ? a0.y : a0.x;  float q0 = (f0 & 1) ? a0.w : a0.z;
            float p1 = (f0 & 1) ? b0.y : b0.x;  float q1 = (f0 & 1) ? b0.w : b0.z;
            float p2 = (f0 & 1) ? c0.y : c0.x;  float q2 = (f0 & 1) ? c0.w : c0.z;
            float p3 = (f0 & 1) ? d0.y : d0.x;  float q3 = (f0 & 1) ? d0.w : d0.z;
            float r0 = (f0 & 2) ? q0 : p0;      float r1 = (f0 & 2) ? q1 : p1;
            float r2 = (f0 & 2) ? q2 : p2;      float r3 = (f0 & 2) ? q3 : p3;
            float u0 = (f0 & 4) ? r1 : r0;      float u1 = (f0 & 4) ? r3 : r2;
            float xv0 = (f0 & 8) ? u1 : u0;

            float P0 = (f1 & 1) ? a1.y : a1.x;  float Q0 = (f1 & 1) ? a1.w : a1.z;
            float P1 = (f1 & 1) ? b1.y : b1.x;  float Q1 = (f1 & 1) ? b1.w : b1.z;
            float P2 = (f1 & 1) ? c1.y : c1.x;  float Q2 = (f1 & 1) ? c1.w : c1.z;
            float P3 = (f1 & 1) ? d1.y : d1.x;  float Q3 = (f1 & 1) ? d1.w : d1.z;
            float R0 = (f1 & 2) ? Q0 : P0;      float R1 = (f1 & 2) ? Q1 : P1;
            float R2 = (f1 & 2) ? Q2 : P2;      float R3 = (f1 & 2) ? Q3 : P3;
            float U0 = (f1 & 4) ? R1 : R0;      float U1 = (f1 & 4) ? R3 : R2;
            float xv1 = (f1 & 8) ? U1 : U0;

            node0 = 2 * node0 + 1 + ((xv0 > __int_as_float(nd0.y)) ? 1 : 0);
            node1 = 2 * node1 + 1 + ((xv1 > __int_as_float(nd1.y)) ? 1 : 0);
        }

        const int myoff0 = (node0 - N_INTERNAL) * (N_CLASSES / 2);
        const int myoff1 = (node1 - N_INTERNAL) * (N_CLASSES / 2);

        // Warp-cooperative coalesced epilogue (float2), offsets via shuffle
        float2* __restrict__ orow0 =
            reinterpret_cast<float2*>(out) + (size_t)(i0 - lane) * (N_CLASSES / 2);
        #pragma unroll
        for (int k = 0; k < 5; ++k) {
            int e  = k * 32 + lane;
            int s  = e / 5;
            int cc = e - s * 5;
            int off = __shfl_sync(0xffffffffu, myoff0, s);
            orow0[e] = lv_s[off + cc];
        }
        if (has1) {
            float2* __restrict__ orow1 =
                reinterpret_cast<float2*>(out) + (size_t)(i1 - lane) * (N_CLASSES / 2);
            #pragma unroll
            for (int k = 0; k < 5; ++k) {
                int e  = k * 32 + lane;
                int s  = e / 5;
                int cc = e - s * 5;
                int off = __shfl_sync(0xffffffffu, myoff1, s);
                orow1[e] = lv_s[off + cc];
            }
        }
    }
}

extern "C" void kernel_launch(void* const* d_in, const int* in_sizes, int n_in,
                              void* d_out, int out_size)
{
    const float* X     = (const float*)d_in[0];
    const int*   tfeat = (const int*)  d_in[1];
    const float* tthr  = (const float*)d_in[2];
    // d_in[3]/d_in[4] (left/right): implicit complete binary tree
    const float* tval  = (const float*)d_in[5];
    // d_in[6] (is_leaf): redundant at depth 10

    float* out = (float*)d_out;
    int n = in_sizes[0] / N_FEATURES;

    static bool attr_set = false;
    if (!attr_set) {
        cudaFuncSetAttribute(dtree_kernel,
                             cudaFuncAttributeMaxDynamicSharedMemorySize, SMEM_BYTES);
        attr_set = true;
    }

    int blocks = (n + BLOCK * 2 - 1) / (BLOCK * 2);
    if (blocks > GRID) blocks = GRID;

    dtree_kernel<<<blocks, BLOCK, SMEM_BYTES>>>(X, tfeat, tthr, tval, out, n);
}

// round 7
// speedup vs baseline: 1.0620x; 1.0603x over previous
#include <cuda_runtime.h>
#include <cstdint>

#define N_FEATURES 16
#define N_CLASSES 10
#define N_INTERNAL 1023
#define N_LEAVES 1024
#define BLOCK 512
#define GRID 456   // 3 CTAs/SM x 152 SMs
#define N_RECORDS 511   // even-level internal nodes live in [0, 511)

// Dynamic smem layout (bytes):
//   [0,     8192)  float4 rec[512]       2-level records {thr_i, thr_L, thr_R, feats}
//   [8192, 49152)  float2 leafvals[5120] (1024 leaf rows x 5 float2)
#define SMEM_BYTES 49152

__global__ __launch_bounds__(BLOCK, 3)
void dtree_kernel(const float* __restrict__ X,
                  const int* __restrict__ tfeat,
                  const float* __restrict__ tthr,
                  const float* __restrict__ tval,
                  float* __restrict__ out,
                  int n)
{
    extern __shared__ char smem_raw[];
    float4* rec_s = reinterpret_cast<float4*>(smem_raw);
    float2* lv_s  = reinterpret_cast<float2*>(smem_raw + 8192);

    const int tid = threadIdx.x;

    // Build 2-level records for even-level nodes i (levels 0,2,4,6,8 all have i < 511).
    // Children 2i+1, 2i+2 are internal (levels 1..9). feats packed: i | L<<4 | R<<8.
    for (int i = tid; i < N_RECORDS; i += BLOCK) {
        int fI = tfeat[i];
        int fL = tfeat[2 * i + 1];
        int fR = tfeat[2 * i + 2];
        rec_s[i] = make_float4(tthr[i], tthr[2 * i + 1], tthr[2 * i + 2],
                               __int_as_float(fI | (fL << 4) | (fR << 8)));
    }
    {
        const float2* tv2 = reinterpret_cast<const float2*>(tval) + (N_INTERNAL * N_CLASSES) / 2;
        for (int i = tid; i < (N_LEAVES * N_CLASSES) / 2; i += BLOCK)
            lv_s[i] = tv2[i];
    }
    __syncthreads();

    const int lane   = tid & 31;
    const int stride = gridDim.x * BLOCK;

    for (int i = blockIdx.x * BLOCK + tid; i < n; i += stride) {
        // 16 features in registers
        const float4* __restrict__ xr = reinterpret_cast<const float4*>(X + (size_t)i * N_FEATURES);
        float4 a = xr[0], b = xr[1], c = xr[2], d = xr[3];

        int node = 0;
        #pragma unroll
        for (int pair = 0; pair < 5; ++pair) {
            float4 rc = rec_s[node];              // one LDS.128 covers two levels
            const int fp = __float_as_int(rc.w);

            // --- level 2*pair: select x[f0] via 4-bit register select tree ---
            const int f0 = fp & 15;
            {
                float s0 = (f0 & 1) ? a.y : a.x;  float s1 = (f0 & 1) ? a.w : a.z;
                float s2 = (f0 & 1) ? b.y : b.x;  float s3 = (f0 & 1) ? b.w : b.z;
                float s4 = (f0 & 1) ? c.y : c.x;  float s5 = (f0 & 1) ? c.w : c.z;
                float s6 = (f0 & 1) ? d.y : d.x;  float s7 = (f0 & 1) ? d.w : d.z;
                float t0 = (f0 & 2) ? s1 : s0;    float t1 = (f0 & 2) ? s3 : s2;
                float t2 = (f0 & 2) ? s5 : s4;    float t3 = (f0 & 2) ? s7 : s6;
                float u0 = (f0 & 4) ? t1 : t0;    float u1 = (f0 & 4) ? t3 : t2;
                float xv0 = (f0 & 8) ? u1 : u0;
                const bool c0 = (xv0 > rc.x);

                // --- level 2*pair+1: child's feat/thr already in registers ---
                const int   f1   = c0 ? ((fp >> 8) & 15) : ((fp >> 4) & 15);
                const float thr1 = c0 ? rc.z : rc.y;
                float v0 = (f1 & 1) ? a.y : a.x;  float v1 = (f1 & 1) ? a.w : a.z;
                float v2 = (f1 & 1) ? b.y : b.x;  float v3 = (f1 & 1) ? b.w : b.z;
                float v4 = (f1 & 1) ? c.y : c.x;  float v5 = (f1 & 1) ? c.w : c.z;
                float v6 = (f1 & 1) ? d.y : d.x;  float v7 = (f1 & 1) ? d.w : d.z;
                float w0 = (f1 & 2) ? v1 : v0;    float w1 = (f1 & 2) ? v3 : v2;
                float w2 = (f1 & 2) ? v5 : v4;    float w3 = (f1 & 2) ? v7 : v6;
                float y0 = (f1 & 4) ? w1 : w0;    float y1 = (f1 & 4) ? w3 : w2;
                float xv1 = (f1 & 8) ? y1 : y0;
                const bool c1 = (xv1 > thr1);

                node = 4 * node + 3 + (c0 ? 2 : 0) + (c1 ? 1 : 0);
            }
        }

        // node in [1023,2047): leaf row offset in float2 units, shared via shuffle
        const int myoff = (node - N_INTERNAL) * (N_CLASSES / 2);

        float2* __restrict__ orow =
            reinterpret_cast<float2*>(out) + (size_t)(i - lane) * (N_CLASSES / 2);
        #pragma unroll
        for (int k = 0; k < 5; ++k) {
            int e  = k * 32 + lane;      // 0..159
            int s  = e / 5;              // sample within warp batch
            int cc = e - s * 5;          // float2 index within row
            int off = __shfl_sync(0xffffffffu, myoff, s);
            orow[e] = lv_s[off + cc];
        }
    }
}

extern "C" void kernel_launch(void* const* d_in, const int* in_sizes, int n_in,
                              void* d_out, int out_size)
{
    const float* X     = (const float*)d_in[0];
    const int*   tfeat = (const int*)  d_in[1];
    const float* tthr  = (const float*)d_in[2];
    // d_in[3]/d_in[4] (left/right): implicit complete binary tree
    const float* tval  = (const float*)d_in[5];
    // d_in[6] (is_leaf): redundant at depth 10

    float* out = (float*)d_out;
    int n = in_sizes[0] / N_FEATURES;

    static bool attr_set = false;
    if (!attr_set) {
        cudaFuncSetAttribute(dtree_kernel,
                             cudaFuncAttributeMaxDynamicSharedMemorySize, SMEM_BYTES);
        attr_set = true;
    }

    int blocks = (n + BLOCK - 1) / BLOCK;
    if (blocks > GRID) blocks = GRID;

    dtree_kernel<<<blocks, BLOCK, SMEM_BYTES>>>(X, tfeat, tthr, tval, out, n);
}

// round 8
// speedup vs baseline: 1.1471x; 1.0801x over previous
#include <cuda_runtime.h>
#include <cstdint>

#define N_FEATURES 16
#define N_CLASSES 10
#define N_INTERNAL 1023
#define BLOCK 512
#define GRID 456   // 3 CTAs/SM x 152 SMs
#define N_RECORDS 511

// Dynamic smem: float4 rec[512] only (8 KB)
#define SMEM_BYTES 8192

__global__ __launch_bounds__(BLOCK, 3)
void dtree_kernel(const float* __restrict__ X,
                  const int* __restrict__ tfeat,
                  const float* __restrict__ tthr,
                  const float* __restrict__ tval,
                  float* __restrict__ out,
                  int n)
{
    extern __shared__ char smem_raw[];
    float4* rec_s = reinterpret_cast<float4*>(smem_raw);

    const int tid = threadIdx.x;

    // 2-level records for even-level nodes i (levels 0,2,4,6,8 -> i < 511).
    // feats packed: fI | fL<<4 | fR<<8.
    for (int i = tid; i < N_RECORDS; i += BLOCK) {
        int fI = tfeat[i];
        int fL = tfeat[2 * i + 1];
        int fR = tfeat[2 * i + 2];
        rec_s[i] = make_float4(tthr[i], tthr[2 * i + 1], tthr[2 * i + 2],
                               __int_as_float(fI | (fL << 4) | (fR << 8)));
    }
    __syncthreads();

    const int lane   = tid & 31;
    const int stride = gridDim.x * BLOCK;
    const float2* __restrict__ tv2 = reinterpret_cast<const float2*>(tval);

    for (int i = blockIdx.x * BLOCK + tid; i < n; i += stride) {
        const float4* __restrict__ xr = reinterpret_cast<const float4*>(X + (size_t)i * N_FEATURES);
        float4 a = xr[0], b = xr[1], c = xr[2], d = xr[3];

        int node = 0;
        #pragma unroll
        for (int pair = 0; pair < 5; ++pair) {
            float4 rc = rec_s[node];              // one LDS.128 covers two levels
            const int fp = __float_as_int(rc.w);

            const int f0 = fp & 15;
            float s0 = (f0 & 1) ? a.y : a.x;  float s1 = (f0 & 1) ? a.w : a.z;
            float s2 = (f0 & 1) ? b.y : b.x;  float s3 = (f0 & 1) ? b.w : b.z;
            float s4 = (f0 & 1) ? c.y : c.x;  float s5 = (f0 & 1) ? c.w : c.z;
            float s6 = (f0 & 1) ? d.y : d.x;  float s7 = (f0 & 1) ? d.w : d.z;
            float t0 = (f0 & 2) ? s1 : s0;    float t1 = (f0 & 2) ? s3 : s2;
            float t2 = (f0 & 2) ? s5 : s4;    float t3 = (f0 & 2) ? s7 : s6;
            float u0 = (f0 & 4) ? t1 : t0;    float u1 = (f0 & 4) ? t3 : t2;
            float xv0 = (f0 & 8) ? u1 : u0;
            const bool c0 = (xv0 > rc.x);

            const int   f1   = c0 ? ((fp >> 8) & 15) : ((fp >> 4) & 15);
            const float thr1 = c0 ? rc.z : rc.y;
            float v0 = (f1 & 1) ? a.y : a.x;  float v1 = (f1 & 1) ? a.w : a.z;
            float v2 = (f1 & 1) ? b.y : b.x;  float v3 = (f1 & 1) ? b.w : b.z;
            float v4 = (f1 & 1) ? c.y : c.x;  float v5 = (f1 & 1) ? c.w : c.z;
            float v6 = (f1 & 1) ? d.y : d.x;  float v7 = (f1 & 1) ? d.w : d.z;
            float w0 = (f1 & 2) ? v1 : v0;    float w1 = (f1 & 2) ? v3 : v2;
            float w2 = (f1 & 2) ? v5 : v4;    float w3 = (f1 & 2) ? v7 : v6;
            float y0 = (f1 & 4) ? w1 : w0;    float y1 = (f1 & 4) ? w3 : w2;
            float xv1 = (f1 & 8) ? y1 : y0;
            const bool c1 = (xv1 > thr1);

            node = 4 * node + 3 + (c0 ? 2 : 0) + (c1 ? 1 : 0);
        }

        // Leaf row base (float2 units) into GLOBAL tval — L2-resident (80 KB).
        const int myoff = node * (N_CLASSES / 2);

        // Warp-cooperative: gather rows from L2, write fully-coalesced.
        float2* __restrict__ orow =
            reinterpret_cast<float2*>(out) + (size_t)(i - lane) * (N_CLASSES / 2);
        #pragma unroll
        for (int k = 0; k < 5; ++k) {
            int e  = k * 32 + lane;      // 0..159
            int s  = e / 5;              // sample within warp batch
            int cc = e - s * 5;          // float2 index within row
            int off = __shfl_sync(0xffffffffu, myoff, s);
            orow[e] = __ldg(&tv2[off + cc]);
        }
    }
}

extern "C" void kernel_launch(void* const* d_in, const int* in_sizes, int n_in,
                              void* d_out, int out_size)
{
    const float* X     = (const float*)d_in[0];
    const int*   tfeat = (const int*)  d_in[1];
    const float* tthr  = (const float*)d_in[2];
    // d_in[3]/d_in[4] (left/right): implicit complete binary tree
    const float* tval  = (const float*)d_in[5];
    // d_in[6] (is_leaf): redundant at depth 10

    float* out = (float*)d_out;
    int n = in_sizes[0] / N_FEATURES;

    static bool attr_set = false;
    if (!attr_set) {
        cudaFuncSetAttribute(dtree_kernel,
                             cudaFuncAttributeMaxDynamicSharedMemorySize, SMEM_BYTES);
        attr_set = true;
    }

    int blocks = (n + BLOCK - 1) / BLOCK;
    if (blocks > GRID) blocks = GRID;

    dtree_kernel<<<blocks, BLOCK, SMEM_BYTES>>>(X, tfeat, tthr, tval, out, n);
}